// round 17
// baseline (speedup 1.0000x reference)
#include <cuda_runtime.h>
#include <cuda_fp16.h>
#include <cstdint>

#define NLVL  10
#define EMB   64
#define NROWS 10002   // 2 zero rows + 10000 table rows

__device__ __align__(16)  float  g_ew[12];             // raw exp(w[l]); [10],[11]=0
__device__ __align__(16)  float  g_al[12];             // prenormalized alphas
__device__ __align__(256) __half g_tab[NROWS * EMB];   // fp16 concept_emb_cat, row=128B

// Convert table fp32->fp16 (rows shifted by +2, rows 0/1 zeroed), exp(w),
// and prenormalized all-available alphas. Early PDL trigger per block.
__global__ void conv_kernel(const float* __restrict__ emb,
                            const float* __restrict__ w, int n16) {
    const int tid = blockIdx.x * blockDim.x + threadIdx.x;
    if (blockIdx.x == 0 && threadIdx.x == 0) {
        float e[NLVL], s = 0.0f;
#pragma unroll
        for (int l = 0; l < NLVL; l++) { e[l] = __expf(w[l]); s += e[l]; }
        const float inv = __frcp_rn(s);
#pragma unroll
        for (int l = 0; l < NLVL; l++) { g_ew[l] = e[l]; g_al[l] = e[l] * inv; }
        g_ew[10] = g_ew[11] = 0.0f;
        g_al[10] = g_al[11] = 0.0f;
    }
    if (blockIdx.x == 0 && threadIdx.x < 16)   // zero rows 0,1
        reinterpret_cast<uint4*>(g_tab)[threadIdx.x] = make_uint4(0u,0u,0u,0u);
    if (tid < n16) {
        const float4* src = reinterpret_cast<const float4*>(emb) + (size_t)tid * 4;
        float4 v[4];
#pragma unroll
        for (int k = 0; k < 4; k++) v[k] = src[k];
        uint4* dst = reinterpret_cast<uint4*>(g_tab + 2 * EMB) + (size_t)tid * 2;
#pragma unroll
        for (int k = 0; k < 2; k++) {
            const __half2 h0 = __floats2half2_rn(v[2*k].x,   v[2*k].y);
            const __half2 h1 = __floats2half2_rn(v[2*k].z,   v[2*k].w);
            const __half2 h2 = __floats2half2_rn(v[2*k+1].x, v[2*k+1].y);
            const __half2 h3 = __floats2half2_rn(v[2*k+1].z, v[2*k+1].w);
            uint4 p;
            p.x = *reinterpret_cast<const unsigned*>(&h0);
            p.y = *reinterpret_cast<const unsigned*>(&h1);
            p.z = *reinterpret_cast<const unsigned*>(&h2);
            p.w = *reinterpret_cast<const unsigned*>(&h3);
            dst[k] = p;
        }
    }
#if __CUDA_ARCH__ >= 900
    __threadfence();
    cudaTriggerProgrammaticLaunchCompletion();
#endif
}

// Two-batch pipelined hot kernel. 8 lanes/token; each 8-lane group owns
// tokens tA (batch 0) and tB = tA+16 (batch 1). Copies for BOTH batches are
// issued up-front in two commit groups; compute/store of A overlaps B's
// arrival. 128-thread CTAs = 32 tokens/block, 40KB static smem.
__global__ __launch_bounds__(128, 5) void kcroute_kernel(
    const int* __restrict__ croutes,   // [ntok, NLVL]
    float*     __restrict__ out,       // [ntok, EMB]
    int ntok)
{
    __shared__ __half stab[4][2][4][NLVL][EMB];  // [warp][batch][tok-in-warp] 40KB

    const int tid = threadIdx.x;
    const int wid = tid >> 5;
    const int tw  = (tid >> 3) & 3;      // token slot within warp (0..3)
    const int qi  = tid & 7;             // 16B slice within the 128B row
    int tokA = blockIdx.x * 32 + (tid >> 3);
    int tokB = tokA + 16;
    const bool vA = (tokA < ntok);
    const bool vB = (tokB < ntok);
    if (!vA) tokA = 0;
    if (!vB) tokB = 0;

    // Index loads for both batches (10 independent LDG.64), before PDL sync.
    const int2* crA = reinterpret_cast<const int2*>(croutes + (size_t)tokA * NLVL);
    const int2* crB = reinterpret_cast<const int2*>(croutes + (size_t)tokB * NLVL);
    const int2 a0 = __ldg(crA+0), a1 = __ldg(crA+1), a2 = __ldg(crA+2),
               a3 = __ldg(crA+3), a4 = __ldg(crA+4);
    const int2 b0 = __ldg(crB+0), b1 = __ldg(crB+1), b2 = __ldg(crB+2),
               b3 = __ldg(crB+3), b4 = __ldg(crB+4);
    const int idxA[NLVL] = { a0.x,a0.y,a1.x,a1.y,a2.x,a2.y,a3.x,a3.y,a4.x,a4.y };
    const int idxB[NLVL] = { b0.x,b0.y,b1.x,b1.y,b2.x,b2.y,b3.x,b3.y,b4.x,b4.y };

#if __CUDA_ARCH__ >= 900
    cudaGridDependencySynchronize();
#endif

    uint32_t sA, sB;
    {
        const void* pA = &stab[wid][0][tw][0][qi * 8];
        const void* pB = &stab[wid][1][tw][0][qi * 8];
        asm("{ .reg .u64 t; cvta.to.shared.u64 t, %1; cvt.u32.u64 %0, t; }"
            : "=r"(sA) : "l"(pA));
        asm("{ .reg .u64 t; cvta.to.shared.u64 t, %1; cvt.u32.u64 %0, t; }"
            : "=r"(sB) : "l"(pB));
    }
    // Batch A copies -> group, Batch B copies -> group.
#pragma unroll
    for (int l = 0; l < NLVL; l++) {
        const __half* gp = g_tab + ((size_t)(idxA[l] + 2)) * EMB + qi * 8;
        asm volatile("cp.async.cg.shared.global [%0], [%1], 16;"
                     :: "r"(sA + l * (EMB * 2)), "l"(gp));
    }
    asm volatile("cp.async.commit_group;");
#pragma unroll
    for (int l = 0; l < NLVL; l++) {
        const __half* gp = g_tab + ((size_t)(idxB[l] + 2)) * EMB + qi * 8;
        asm volatile("cp.async.cg.shared.global [%0], [%1], 16;"
                     :: "r"(sB + l * (EMB * 2)), "l"(gp));
    }
    asm volatile("cp.async.commit_group;");

    // Alphas: fast path = prenormalized (all levels available for this data).
    bool badA = false, badB = false;
#pragma unroll
    for (int l = 0; l < NLVL; l++) { badA |= (idxA[l] == -2); badB |= (idxB[l] == -2); }

    const float4 la = *reinterpret_cast<const float4*>(&g_al[0]);
    const float4 lb = *reinterpret_cast<const float4*>(&g_al[4]);
    const float2 lc = *reinterpret_cast<const float2*>(&g_al[8]);
    float alA[NLVL] = { la.x,la.y,la.z,la.w, lb.x,lb.y,lb.z,lb.w, lc.x,lc.y };
    float alB[NLVL] = { la.x,la.y,la.z,la.w, lb.x,lb.y,lb.z,lb.w, lc.x,lc.y };
    if (__builtin_expect(badA || badB, 0)) {
        const float4 ea = *reinterpret_cast<const float4*>(&g_ew[0]);
        const float4 eb = *reinterpret_cast<const float4*>(&g_ew[4]);
        const float2 ec = *reinterpret_cast<const float2*>(&g_ew[8]);
        const float e[NLVL] = { ea.x,ea.y,ea.z,ea.w, eb.x,eb.y,eb.z,eb.w, ec.x,ec.y };
        float sAd = 0.f, sBd = 0.f;
#pragma unroll
        for (int l = 0; l < NLVL; l++) {
            sAd += (idxA[l] != -2) ? e[l] : 0.0f;
            sBd += (idxB[l] != -2) ? e[l] : 0.0f;
        }
        const float iA = (sAd > 0.f) ? __frcp_rn(sAd) : 0.0f;
        const float iB = (sBd > 0.f) ? __frcp_rn(sBd) : 0.0f;
#pragma unroll
        for (int l = 0; l < NLVL; l++) {
            alA[l] = (idxA[l] != -2) ? e[l] * iA : 0.0f;
            alB[l] = (idxB[l] != -2) ? e[l] * iB : 0.0f;
        }
    }

    // ---- Batch A: wait (B still in flight), compute, store ----
    float acc[8] = {0.f,0.f,0.f,0.f,0.f,0.f,0.f,0.f};
    asm volatile("cp.async.wait_group 1;");
    __syncwarp();
#pragma unroll
    for (int l = 0; l < NLVL; l++) {
        const uint4 v = *reinterpret_cast<const uint4*>(&stab[wid][0][tw][l][qi * 8]);
        const float2 a = __half22float2(*reinterpret_cast<const __half2*>(&v.x));
        const float2 b = __half22float2(*reinterpret_cast<const __half2*>(&v.y));
        const float2 c = __half22float2(*reinterpret_cast<const __half2*>(&v.z));
        const float2 d = __half22float2(*reinterpret_cast<const __half2*>(&v.w));
        acc[0] = fmaf(alA[l], a.x, acc[0]);
        acc[1] = fmaf(alA[l], a.y, acc[1]);
        acc[2] = fmaf(alA[l], b.x, acc[2]);
        acc[3] = fmaf(alA[l], b.y, acc[3]);
        acc[4] = fmaf(alA[l], c.x, acc[4]);
        acc[5] = fmaf(alA[l], c.y, acc[5]);
        acc[6] = fmaf(alA[l], d.x, acc[6]);
        acc[7] = fmaf(alA[l], d.y, acc[7]);
    }
    if (vA) {
        float* op = out + (size_t)tokA * EMB + qi * 8;
        *reinterpret_cast<float4*>(op)     = make_float4(acc[0],acc[1],acc[2],acc[3]);
        *reinterpret_cast<float4*>(op + 4) = make_float4(acc[4],acc[5],acc[6],acc[7]);
    }

    // ---- Batch B: wait, compute, store ----
#pragma unroll
    for (int k = 0; k < 8; k++) acc[k] = 0.0f;
    asm volatile("cp.async.wait_group 0;");
    __syncwarp();
#pragma unroll
    for (int l = 0; l < NLVL; l++) {
        const uint4 v = *reinterpret_cast<const uint4*>(&stab[wid][1][tw][l][qi * 8]);
        const float2 a = __half22float2(*reinterpret_cast<const __half2*>(&v.x));
        const float2 b = __half22float2(*reinterpret_cast<const __half2*>(&v.y));
        const float2 c = __half22float2(*reinterpret_cast<const __half2*>(&v.z));
        const float2 d = __half22float2(*reinterpret_cast<const __half2*>(&v.w));
        acc[0] = fmaf(alB[l], a.x, acc[0]);
        acc[1] = fmaf(alB[l], a.y, acc[1]);
        acc[2] = fmaf(alB[l], b.x, acc[2]);
        acc[3] = fmaf(alB[l], b.y, acc[3]);
        acc[4] = fmaf(alB[l], c.x, acc[4]);
        acc[5] = fmaf(alB[l], c.y, acc[5]);
        acc[6] = fmaf(alB[l], d.x, acc[6]);
        acc[7] = fmaf(alB[l], d.y, acc[7]);
    }
    if (vB) {
        float* op = out + (size_t)tokB * EMB + qi * 8;
        *reinterpret_cast<float4*>(op)     = make_float4(acc[0],acc[1],acc[2],acc[3]);
        *reinterpret_cast<float4*>(op + 4) = make_float4(acc[4],acc[5],acc[6],acc[7]);
    }
}

extern "C" void kernel_launch(void* const* d_in, const int* in_sizes, int n_in,
                              void* d_out, int out_size) {
    const int*   croutes = (const int*)d_in[0];
    // d_in[1] (tailcs) unused by the reference computation.
    const float* emb     = (const float*)d_in[2];
    const float* w       = (const float*)d_in[3];
    float*       out     = (float*)d_out;

    const int ntok = in_sizes[1];                 // B * S
    const int n16  = in_sizes[2] / 16;            // table 16-float chunks
    conv_kernel<<<(n16 + 255) / 256, 256>>>(emb, w, n16);

    const int blocks = (ntok + 31) / 32;          // 32 tokens per 128-thread block

    cudaLaunchConfig_t cfg = {};
    cfg.gridDim  = dim3((unsigned)blocks, 1, 1);
    cfg.blockDim = dim3(128, 1, 1);
    cudaLaunchAttribute attr[1];
    attr[0].id = cudaLaunchAttributeProgrammaticStreamSerialization;
    attr[0].val.programmaticStreamSerializationAllowed = 1;
    cfg.attrs    = attr;
    cfg.numAttrs = 1;
    cudaError_t err = cudaLaunchKernelEx(&cfg, kcroute_kernel, croutes, out, ntok);
    if (err != cudaSuccess) {
        kcroute_kernel<<<blocks, 128>>>(croutes, out, ntok);
    }
}